// round 2
// baseline (speedup 1.0000x reference)
#include <cuda_runtime.h>
#include <cstdint>

#define BB 8
#define CHN 512
#define HH 80
#define WWD 80
#define CR 32
#define HW 6400
#define KDIM 1024

#define BM 128
#define BN 128
#define BK 16
#define ASTR 20      // As row stride (floats): conflict-free for A-frag reads
#define BSTR 136     // Bs row stride (floats): conflict-free for B-frag reads
#define NTILES (KDIM / BK)

// ---------------- device scratch ----------------
__device__ float g_meanh[2][BB][CHN][HH];   // mean over w, per h  (rgb:0 / t:1)
__device__ float g_meanw[2][BB][CHN][WWD];  // mean over h, per w
__device__ float g_y[2][BB][CR][160];       // y (bn+relu) / z (relu)
__device__ float g_gh[2][BB][CHN][HH];      // sigmoid gates (h-direction)
__device__ float g_gw[2][BB][CHN][WWD];     // sigmoid gates (w-direction)

// ---------------- ptx helpers ----------------
__device__ __forceinline__ void cp_async16(void* smem, const void* gmem) {
    uint32_t s = (uint32_t)__cvta_generic_to_shared(smem);
    asm volatile("cp.async.cg.shared.global [%0], [%1], 16;\n" :: "r"(s), "l"(gmem));
}
__device__ __forceinline__ void cp_commit() {
    asm volatile("cp.async.commit_group;\n");
}
__device__ __forceinline__ void cp_wait1() {
    asm volatile("cp.async.wait_group 1;\n");
}
__device__ __forceinline__ void cp_wait0() {
    asm volatile("cp.async.wait_group 0;\n");
}
__device__ __forceinline__ uint32_t f2tf32(float x) {
    uint32_t r;
    asm("cvt.rna.tf32.f32 %0, %1;\n" : "=r"(r) : "f"(x));
    return r;
}
__device__ __forceinline__ void mma_tf32(float* c, const uint32_t* a, const uint32_t* b) {
    asm volatile(
        "mma.sync.aligned.m16n8k8.row.col.f32.tf32.tf32.f32 "
        "{%0,%1,%2,%3}, {%4,%5,%6,%7}, {%8,%9}, {%0,%1,%2,%3};\n"
        : "+f"(c[0]), "+f"(c[1]), "+f"(c[2]), "+f"(c[3])
        : "r"(a[0]), "r"(a[1]), "r"(a[2]), "r"(a[3]), "r"(b[0]), "r"(b[1]));
}

// ---------------- kernel 1: row/col means of rgb and t ----------------
// grid = 2*B*CHN blocks, 256 threads. One (which,b,c) plane per block.
__global__ void reduce_kernel(const float* __restrict__ rgb, const float* __restrict__ t) {
    __shared__ float sp[80 * 81];   // padded stride 81: conflict-free both directions
    int idx = blockIdx.x;
    int which = idx >> 12;          // 4096 planes per tensor
    int pc = idx & 4095;
    int b = pc >> 9, c = pc & 511;
    const float* src = (which ? t : rgb) + (size_t)(b * CHN + c) * HW;

    const float4* s4 = (const float4*)src;
    for (int i = threadIdx.x; i < 1600; i += blockDim.x) {
        float4 v = s4[i];
        int e = i * 4;
        int h = e / 80, w = e - h * 80;   // w % 4 == 0, rows of 80 divisible by 4
        float* d = &sp[h * 81 + w];
        d[0] = v.x; d[1] = v.y; d[2] = v.z; d[3] = v.w;
    }
    __syncthreads();

    int tx = threadIdx.x;
    if (tx < 80) {
        float cs = 0.f, rs = 0.f;
        #pragma unroll 8
        for (int h = 0; h < 80; h++) cs += sp[h * 81 + tx];
        #pragma unroll 8
        for (int w = 0; w < 80; w++) rs += sp[tx * 81 + w];
        g_meanw[which][b][c][tx] = cs * (1.f / 80.f);  // mean over h (axis=2)
        g_meanh[which][b][c][tx] = rs * (1.f / 80.f);  // mean over w (axis=3)
    }
}

// ---------------- kernel 2: y = bn(relu?) of [32x512]@[512x160] ----------------
// grid = (16, 4): x = which*8+b, y = group of 8 output channels. 160 threads.
__global__ void yz_kernel(const float* __restrict__ w_r1, const float* __restrict__ w_t1,
                          const float* __restrict__ bn_gamma, const float* __restrict__ bn_beta,
                          const float* __restrict__ bn_mean, const float* __restrict__ bn_var) {
    __shared__ float ws[8 * 512];
    int which = blockIdx.x >> 3;
    int b = blockIdx.x & 7;
    int ig = blockIdx.y;            // output rows ig*8 .. ig*8+7
    const float* w = (which ? w_t1 : w_r1) + ig * 8 * 512;
    for (int i = threadIdx.x; i < 8 * 512; i += blockDim.x) ws[i] = w[i];
    __syncthreads();

    int p = threadIdx.x;            // spatial position 0..159
    if (p >= 160) return;
    const float* m = (p < 80) ? (&g_meanh[which][b][0][0] + p)
                              : (&g_meanw[which][b][0][0] + (p - 80));
    float acc[8] = {0.f, 0.f, 0.f, 0.f, 0.f, 0.f, 0.f, 0.f};
    for (int c = 0; c < 512; c++) {
        float mv = m[c * 80];
        #pragma unroll
        for (int i = 0; i < 8; i++) acc[i] += ws[i * 512 + c] * mv;
    }
    #pragma unroll
    for (int i = 0; i < 8; i++) {
        int oi = ig * 8 + i;
        float v = acc[i];
        if (which == 0) {
            float inv = rsqrtf(bn_var[oi] + 1e-5f);
            float sc = bn_gamma[oi] * inv;
            float sh = bn_beta[oi] - bn_gamma[oi] * bn_mean[oi] * inv;
            v = v * sc + sh;
        }
        v = fmaxf(v, 0.f);
        g_y[which][b][oi][p] = v;
    }
}

// ---------------- kernel 3: sigmoid gates, [512x32]@[32x80] x4 ----------------
// grid = 16 (which*8+b), 512 threads (one output channel each).
__global__ void gates_kernel(const float* __restrict__ w_fh1, const float* __restrict__ w_fw1,
                             const float* __restrict__ w_fh2, const float* __restrict__ w_fw2) {
    __shared__ float ys[CR * 160];
    int which = blockIdx.x >> 3, b = blockIdx.x & 7;
    const float* y = &g_y[which][b][0][0];
    for (int i = threadIdx.x; i < CR * 160; i += blockDim.x) ys[i] = y[i];
    __syncthreads();

    int o = threadIdx.x;  // 0..511
    const float* whp = (which ? w_fh2 : w_fh1) + o * CR;
    const float* wwp = (which ? w_fw2 : w_fw1) + o * CR;
    float wh[CR], wwr[CR];
    #pragma unroll
    for (int i = 0; i < CR; i++) { wh[i] = whp[i]; wwr[i] = wwp[i]; }

    for (int h = 0; h < 80; h++) {
        float a = 0.f;
        #pragma unroll
        for (int i = 0; i < CR; i++) a += wh[i] * ys[i * 160 + h];
        g_gh[which][b][o][h] = 1.f / (1.f + __expf(-a));
    }
    for (int w = 0; w < 80; w++) {
        float a = 0.f;
        #pragma unroll
        for (int i = 0; i < CR; i++) a += wwr[i] * ys[i * 160 + 80 + w];
        g_gw[which][b][o][w] = 1.f / (1.f + __expf(-a));
    }
}

// ---------------- kernel 4: main GEMM (tf32 mma.sync) + fused gate epilogue ----
// Per batch: C[512,6400] = Wfuse[512,1024] @ X[1024,6400], X = rgb(0:512) | t(512:1024)
// grid = (50, 4, 8), 256 threads (8 warps as 2x4, warp tile 64x32).
__global__ __launch_bounds__(256, 2)
void gemm_kernel(const float* __restrict__ rgb, const float* __restrict__ t,
                 const float* __restrict__ wfuse, float* __restrict__ out) {
    __shared__ float As[2][BM][ASTR];
    __shared__ float Bs[2][BK][BSTR];

    int n0 = blockIdx.x * BN;
    int m0 = blockIdx.y * BM;
    int b  = blockIdx.z;
    const float* rgbb = rgb + (size_t)b * CHN * HW;
    const float* tb   = t   + (size_t)b * CHN * HW;

    int tid = threadIdx.x;
    int lane = tid & 31, warp = tid >> 5;
    int wm = warp >> 2, wn = warp & 3;

    // global->smem mapping
    int ar  = tid >> 1;            // 0..127 (A row)
    int ac4 = (tid & 1) * 4;       // A col start {0,4}; second copy +8
    int br  = tid >> 4;            // 0..15  (B row)
    int bc4 = (tid & 15) * 4;      // B col start; second copy +64

    float acc[4][4][4];
    #pragma unroll
    for (int i = 0; i < 4; i++)
        #pragma unroll
        for (int j = 0; j < 4; j++)
            #pragma unroll
            for (int e = 0; e < 4; e++) acc[i][j][e] = 0.f;

    auto load_tile = [&](int kt, int buf) {
        int k0 = kt * BK;
        const float* asrc = wfuse + (size_t)(m0 + ar) * KDIM + k0;
        cp_async16(&As[buf][ar][ac4],     asrc + ac4);
        cp_async16(&As[buf][ar][ac4 + 8], asrc + ac4 + 8);
        int k = k0 + br;
        const float* bsrc = (k < 512 ? rgbb + (size_t)k * HW
                                     : tb + (size_t)(k - 512) * HW) + n0;
        cp_async16(&Bs[buf][br][bc4],      bsrc + bc4);
        cp_async16(&Bs[buf][br][bc4 + 64], bsrc + bc4 + 64);
        cp_commit();
    };

    load_tile(0, 0);

    for (int kt = 0; kt < NTILES; kt++) {
        int buf = kt & 1;
        if (kt + 1 < NTILES) {
            load_tile(kt + 1, buf ^ 1);
            cp_wait1();
        } else {
            cp_wait0();
        }
        __syncthreads();

        #pragma unroll
        for (int s = 0; s < 2; s++) {
            int kr = s * 8 + (lane & 3);
            int mr = wm * 64 + (lane >> 2);
            uint32_t a[4][4], bf[4][2];
            #pragma unroll
            for (int i = 0; i < 4; i++) {
                int m = mr + i * 16;
                a[i][0] = f2tf32(As[buf][m][kr]);
                a[i][1] = f2tf32(As[buf][m + 8][kr]);
                a[i][2] = f2tf32(As[buf][m][kr + 4]);
                a[i][3] = f2tf32(As[buf][m + 8][kr + 4]);
            }
            #pragma unroll
            for (int j = 0; j < 4; j++) {
                int nc = wn * 32 + j * 8 + (lane >> 2);
                bf[j][0] = f2tf32(Bs[buf][kr][nc]);
                bf[j][1] = f2tf32(Bs[buf][kr + 4][nc]);
            }
            #pragma unroll
            for (int i = 0; i < 4; i++)
                #pragma unroll
                for (int j = 0; j < 4; j++)
                    mma_tf32(acc[i][j], a[i], bf[j]);
        }
        __syncthreads();
    }

    // epilogue: out = c * (s1h*s1w + s2h*s2w), float2 stores
    const float* gh1 = &g_gh[0][b][0][0];
    const float* gw1 = &g_gw[0][b][0][0];
    const float* gh2 = &g_gh[1][b][0][0];
    const float* gw2 = &g_gw[1][b][0][0];
    float* outb = out + (size_t)b * CHN * HW;

    #pragma unroll
    for (int i = 0; i < 4; i++) {
        int r0 = m0 + wm * 64 + i * 16 + (lane >> 2);
        #pragma unroll
        for (int j = 0; j < 4; j++) {
            int c0 = n0 + wn * 32 + j * 8 + 2 * (lane & 3);
            int h = c0 / 80;
            int w0 = c0 - h * 80;       // c0 even -> pair never crosses a row of 80
            #pragma unroll
            for (int rr = 0; rr < 2; rr++) {
                int r = r0 + rr * 8;
                float gA = __ldg(&gh1[r * 80 + h]);
                float gB = __ldg(&gh2[r * 80 + h]);
                float gv0 = gA * __ldg(&gw1[r * 80 + w0])     + gB * __ldg(&gw2[r * 80 + w0]);
                float gv1 = gA * __ldg(&gw1[r * 80 + w0 + 1]) + gB * __ldg(&gw2[r * 80 + w0 + 1]);
                float2 v = make_float2(acc[i][j][rr * 2 + 0] * gv0,
                                       acc[i][j][rr * 2 + 1] * gv1);
                *(float2*)&outb[(size_t)r * HW + c0] = v;
            }
        }
    }
}

// ---------------- launch ----------------
extern "C" void kernel_launch(void* const* d_in, const int* in_sizes, int n_in,
                              void* d_out, int out_size) {
    const float* rgb      = (const float*)d_in[0];
    const float* t        = (const float*)d_in[1];
    const float* w_fuse   = (const float*)d_in[2];
    const float* w_r1     = (const float*)d_in[3];
    const float* w_t1     = (const float*)d_in[4];
    const float* w_fh1    = (const float*)d_in[5];
    const float* w_fw1    = (const float*)d_in[6];
    const float* w_fh2    = (const float*)d_in[7];
    const float* w_fw2    = (const float*)d_in[8];
    const float* bn_gamma = (const float*)d_in[9];
    const float* bn_beta  = (const float*)d_in[10];
    const float* bn_mean  = (const float*)d_in[11];
    const float* bn_var   = (const float*)d_in[12];
    float* out = (float*)d_out;

    reduce_kernel<<<2 * BB * CHN, 256>>>(rgb, t);
    yz_kernel<<<dim3(16, 4), 160>>>(w_r1, w_t1, bn_gamma, bn_beta, bn_mean, bn_var);
    gates_kernel<<<16, 512>>>(w_fh1, w_fw1, w_fh2, w_fw2);
    gemm_kernel<<<dim3(HW / BN, CHN / BM, BB), 256>>>(rgb, t, w_fuse, out);
}

// round 17
// speedup vs baseline: 1.1813x; 1.1813x over previous
#include <cuda_runtime.h>
#include <cstdint>

#define BB 8
#define CHN 512
#define HH 80
#define WWD 80
#define CR 32
#define HW 6400
#define KDIM 1024

#define BM 128
#define BN 128
#define BK 16
#define ASTR 20      // As row stride (floats): conflict-free for A-frag reads
#define BSTR 136     // Bs row stride (floats): conflict-free for B-frag reads
#define NTILES (KDIM / BK)
#define STAGES 4
#define A_STAGE (BM * ASTR)                    // 2560 floats
#define B_STAGE (BK * BSTR)                    // 2176 floats
#define B_BASE  (STAGES * A_STAGE)             // 10240 floats
#define SMEM_FLOATS (B_BASE + STAGES * B_STAGE)
#define SMEM_BYTES (SMEM_FLOATS * 4)           // 75776 bytes (dynamic)

// ---------------- device scratch ----------------
__device__ float g_meanh[2][BB][CHN][HH];   // mean over w, per h  (rgb:0 / t:1)
__device__ float g_meanw[2][BB][CHN][WWD];  // mean over h, per w
__device__ float g_y[2][BB][CR][160];       // y (bn+relu) / z (relu)
__device__ float g_gh[2][BB][HH][CHN];      // sigmoid gates, [pos][channel] (coalesced)
__device__ float g_gw[2][BB][WWD][CHN];

// ---------------- ptx helpers ----------------
__device__ __forceinline__ void cp_async16(void* smem, const void* gmem) {
    uint32_t s = (uint32_t)__cvta_generic_to_shared(smem);
    asm volatile("cp.async.cg.shared.global [%0], [%1], 16;\n" :: "r"(s), "l"(gmem));
}
__device__ __forceinline__ void cp_commit() {
    asm volatile("cp.async.commit_group;\n");
}
__device__ __forceinline__ void cp_wait2() {
    asm volatile("cp.async.wait_group 2;\n");
}
__device__ __forceinline__ uint32_t f2tf32(float x) {
    uint32_t r;
    asm("cvt.rna.tf32.f32 %0, %1;\n" : "=r"(r) : "f"(x));
    return r;
}
__device__ __forceinline__ void mma_tf32(float* c, const uint32_t* a, const uint32_t* b) {
    asm volatile(
        "mma.sync.aligned.m16n8k8.row.col.f32.tf32.tf32.f32 "
        "{%0,%1,%2,%3}, {%4,%5,%6,%7}, {%8,%9}, {%0,%1,%2,%3};\n"
        : "+f"(c[0]), "+f"(c[1]), "+f"(c[2]), "+f"(c[3])
        : "r"(a[0]), "r"(a[1]), "r"(a[2]), "r"(a[3]), "r"(b[0]), "r"(b[1]));
}

// ---------------- kernel 1: row/col means of rgb and t ----------------
// grid = 2*B*CHN blocks, 256 threads. One (which,b,c) plane per block.
__global__ void reduce_kernel(const float* __restrict__ rgb, const float* __restrict__ t) {
    __shared__ float sp[80 * 81];   // padded stride 81: conflict-free both directions
    int idx = blockIdx.x;
    int which = idx >> 12;          // 4096 planes per tensor
    int pc = idx & 4095;
    int b = pc >> 9, c = pc & 511;
    const float* src = (which ? t : rgb) + (size_t)(b * CHN + c) * HW;

    const float4* s4 = (const float4*)src;
    #pragma unroll
    for (int it = 0; it < 7; it++) {
        int i = it * 256 + threadIdx.x;
        if (i < 1600) {
            float4 v = s4[i];
            int e = i * 4;
            int h = e / 80, w = e - h * 80;   // w % 4 == 0
            float* d = &sp[h * 81 + w];
            d[0] = v.x; d[1] = v.y; d[2] = v.z; d[3] = v.w;
        }
    }
    __syncthreads();

    int tx = threadIdx.x;
    if (tx < 80) {                           // column sums (mean over h)
        float cs = 0.f;
        #pragma unroll 16
        for (int h = 0; h < 80; h++) cs += sp[h * 81 + tx];
        g_meanw[which][b][c][tx] = cs * (1.f / 80.f);
    } else if (tx >= 128 && tx < 208) {      // row sums (mean over w), separate warps
        int h = tx - 128;
        float rs = 0.f;
        #pragma unroll 16
        for (int w = 0; w < 80; w++) rs += sp[h * 81 + w];
        g_meanh[which][b][c][h] = rs * (1.f / 80.f);
    }
}

// ---------------- kernel 2: y/z = act([32x512]@[512x160]) ----------------
// grid = (16, 8): x = which*8+b, y = group of 4 output channels. 160 threads.
__global__ void yz_kernel(const float* __restrict__ w_r1, const float* __restrict__ w_t1,
                          const float* __restrict__ bn_gamma, const float* __restrict__ bn_beta,
                          const float* __restrict__ bn_mean, const float* __restrict__ bn_var) {
    __shared__ float ws[4 * 512];
    int which = blockIdx.x >> 3;
    int b = blockIdx.x & 7;
    int ig = blockIdx.y;            // output rows ig*4 .. ig*4+3
    const float* w = (which ? w_t1 : w_r1) + ig * 4 * 512;
    for (int i = threadIdx.x; i < 4 * 512; i += blockDim.x) ws[i] = w[i];
    __syncthreads();

    int p = threadIdx.x;            // spatial position 0..159
    if (p >= 160) return;
    const float* m = (p < 80) ? (&g_meanh[which][b][0][0] + p)
                              : (&g_meanw[which][b][0][0] + (p - 80));
    float acc[4] = {0.f, 0.f, 0.f, 0.f};
    #pragma unroll 8
    for (int c = 0; c < 512; c++) {
        float mv = m[c * 80];
        #pragma unroll
        for (int i = 0; i < 4; i++) acc[i] += ws[i * 512 + c] * mv;
    }
    #pragma unroll
    for (int i = 0; i < 4; i++) {
        int oi = ig * 4 + i;
        float v = acc[i];
        if (which == 0) {
            float inv = rsqrtf(bn_var[oi] + 1e-5f);
            float sc = bn_gamma[oi] * inv;
            float sh = bn_beta[oi] - bn_gamma[oi] * bn_mean[oi] * inv;
            v = v * sc + sh;
        }
        v = fmaxf(v, 0.f);
        g_y[which][b][oi][p] = v;
    }
}

// ---------------- kernel 3: sigmoid gates ----------------
// grid = (16, 20): x = which*8+b, y = group of 8 positions. 512 threads (1 per out-chan).
// Writes transposed layout [pos][chan] -> coalesced stores AND coalesced epilogue reads.
__global__ void gates_kernel(const float* __restrict__ w_fh1, const float* __restrict__ w_fw1,
                             const float* __restrict__ w_fh2, const float* __restrict__ w_fw2) {
    __shared__ float ys[8][CR];
    int which = blockIdx.x >> 3, b = blockIdx.x & 7;
    int p0 = blockIdx.y * 8;
    int tid = threadIdx.x;
    if (tid < 256) {
        int i = tid >> 3, pp = tid & 7;
        ys[pp][i] = g_y[which][b][i][p0 + pp];
    }
    __syncthreads();

    bool is_h = (p0 < 80);
    const float* wsel = is_h ? (which ? w_fh2 : w_fh1) : (which ? w_fw2 : w_fw1);
    float wreg[CR];
    #pragma unroll
    for (int i = 0; i < CR; i++) wreg[i] = wsel[tid * CR + i];

    #pragma unroll
    for (int pp = 0; pp < 8; pp++) {
        float a = 0.f;
        #pragma unroll
        for (int i = 0; i < CR; i++) a += wreg[i] * ys[pp][i];
        float s = 1.f / (1.f + __expf(-a));
        if (is_h) g_gh[which][b][p0 + pp][tid] = s;
        else      g_gw[which][b][p0 + pp - 80][tid] = s;
    }
}

// ---------------- kernel 4: main GEMM (tf32 mma.sync, 4-stage dynamic smem) ----
// Per batch: C[512,6400] = Wfuse[512,1024] @ X[1024,6400], X = rgb(0:512) | t(512:1024)
// grid = (50, 4, 8), 256 threads (8 warps as 2x4, warp tile 64x32).
// Pipeline order per iter: wait(own groups) -> barrier(publish) -> compute -> prefetch.
__global__ __launch_bounds__(256, 2)
void gemm_kernel(const float* __restrict__ rgb, const float* __restrict__ t,
                 const float* __restrict__ wfuse, float* __restrict__ out) {
    extern __shared__ float smem[];   // [STAGES][BM][ASTR] then [STAGES][BK][BSTR]

    int n0 = blockIdx.x * BN;
    int m0 = blockIdx.y * BM;
    int b  = blockIdx.z;
    const float* rgbb = rgb + (size_t)b * CHN * HW;
    const float* tb   = t   + (size_t)b * CHN * HW;

    int tid = threadIdx.x;
    int lane = tid & 31, warp = tid >> 5;
    int wm = warp >> 2, wn = warp & 3;

    // global->smem mapping
    int ar  = tid >> 1;            // 0..127 (A row)
    int ac4 = (tid & 1) * 4;       // A col start {0,4}; second copy +8
    int br  = tid >> 4;            // 0..15  (B row)
    int bc4 = (tid & 15) * 4;      // B col start; second copy +64

    float acc[4][4][4];
    #pragma unroll
    for (int i = 0; i < 4; i++)
        #pragma unroll
        for (int j = 0; j < 4; j++)
            #pragma unroll
            for (int e = 0; e < 4; e++) acc[i][j][e] = 0.f;

    auto load_tile = [&](int kt, int buf) {
        int k0 = kt * BK;
        float* As = smem + buf * A_STAGE;
        float* Bs = smem + B_BASE + buf * B_STAGE;
        const float* asrc = wfuse + (size_t)(m0 + ar) * KDIM + k0;
        cp_async16(&As[ar * ASTR + ac4],     asrc + ac4);
        cp_async16(&As[ar * ASTR + ac4 + 8], asrc + ac4 + 8);
        // BK=16 tiles never straddle the 512 boundary
        const float* xb = (k0 < 512) ? (rgbb + (size_t)k0 * HW) : (tb + (size_t)(k0 - 512) * HW);
        const float* bsrc = xb + (size_t)br * HW + n0;
        cp_async16(&Bs[br * BSTR + bc4],      bsrc + bc4);
        cp_async16(&Bs[br * BSTR + bc4 + 64], bsrc + bc4 + 64);
        cp_commit();
    };

    load_tile(0, 0);
    load_tile(1, 1);
    load_tile(2, 2);

    for (int kt = 0; kt < NTILES; kt++) {
        cp_wait2();        // own groups <= kt complete (3+kt committed, 2 pending)
        __syncthreads();   // publish: every thread's tile-kt copies now visible
        int buf = kt % STAGES;
        const float* As = smem + buf * A_STAGE;
        const float* Bs = smem + B_BASE + buf * B_STAGE;

        #pragma unroll
        for (int s = 0; s < 2; s++) {
            int kr = s * 8 + (lane & 3);
            int mr = wm * 64 + (lane >> 2);
            uint32_t a[4][4], bf[4][2];
            #pragma unroll
            for (int i = 0; i < 4; i++) {
                int m = mr + i * 16;
                a[i][0] = f2tf32(As[m * ASTR + kr]);
                a[i][1] = f2tf32(As[(m + 8) * ASTR + kr]);
                a[i][2] = f2tf32(As[m * ASTR + kr + 4]);
                a[i][3] = f2tf32(As[(m + 8) * ASTR + kr + 4]);
            }
            #pragma unroll
            for (int j = 0; j < 4; j++) {
                int nc = wn * 32 + j * 8 + (lane >> 2);
                bf[j][0] = f2tf32(Bs[kr * BSTR + nc]);
                bf[j][1] = f2tf32(Bs[(kr + 4) * BSTR + nc]);
            }
            #pragma unroll
            for (int i = 0; i < 4; i++)
                #pragma unroll
                for (int j = 0; j < 4; j++)
                    mma_tf32(acc[i][j], a[i], bf[j]);
        }

        // prefetch tile kt+3 into buffer (kt+3)%4 == (kt-1)%4, freed by this
        // iteration's barrier (all warps finished compute(kt-1) before it).
        if (kt + 3 < NTILES) load_tile(kt + 3, (kt + 3) % STAGES);
        else cp_commit();  // keep group numbering uniform
    }

    // epilogue: out = c * (s1h*s1w + s2h*s2w). gates are [pos][chan] -> coalesced reads.
    const float* gh1 = &g_gh[0][b][0][0];
    const float* gw1 = &g_gw[0][b][0][0];
    const float* gh2 = &g_gh[1][b][0][0];
    const float* gw2 = &g_gw[1][b][0][0];
    float* outb = out + (size_t)b * CHN * HW;

    #pragma unroll
    for (int i = 0; i < 4; i++) {
        int r0 = m0 + wm * 64 + i * 16 + (lane >> 2);
        #pragma unroll
        for (int j = 0; j < 4; j++) {
            int c0 = n0 + wn * 32 + j * 8 + 2 * (lane & 3);
            int h = c0 / 80;
            int w0 = c0 - h * 80;       // c0 even -> pair never crosses a row of 80
            #pragma unroll
            for (int rr = 0; rr < 2; rr++) {
                int r = r0 + rr * 8;
                float gA = __ldg(&gh1[h * CHN + r]);
                float gB = __ldg(&gh2[h * CHN + r]);
                float gv0 = gA * __ldg(&gw1[w0 * CHN + r])       + gB * __ldg(&gw2[w0 * CHN + r]);
                float gv1 = gA * __ldg(&gw1[(w0 + 1) * CHN + r]) + gB * __ldg(&gw2[(w0 + 1) * CHN + r]);
                float2 v = make_float2(acc[i][j][rr * 2 + 0] * gv0,
                                       acc[i][j][rr * 2 + 1] * gv1);
                *(float2*)&outb[(size_t)r * HW + c0] = v;
            }
        }
    }
}

// ---------------- launch ----------------
extern "C" void kernel_launch(void* const* d_in, const int* in_sizes, int n_in,
                              void* d_out, int out_size) {
    const float* rgb      = (const float*)d_in[0];
    const float* t        = (const float*)d_in[1];
    const float* w_fuse   = (const float*)d_in[2];
    const float* w_r1     = (const float*)d_in[3];
    const float* w_t1     = (const float*)d_in[4];
    const float* w_fh1    = (const float*)d_in[5];
    const float* w_fw1    = (const float*)d_in[6];
    const float* w_fh2    = (const float*)d_in[7];
    const float* w_fw2    = (const float*)d_in[8];
    const float* bn_gamma = (const float*)d_in[9];
    const float* bn_beta  = (const float*)d_in[10];
    const float* bn_mean  = (const float*)d_in[11];
    const float* bn_var   = (const float*)d_in[12];
    float* out = (float*)d_out;

    cudaFuncSetAttribute(gemm_kernel, cudaFuncAttributeMaxDynamicSharedMemorySize, SMEM_BYTES);

    reduce_kernel<<<2 * BB * CHN, 256>>>(rgb, t);
    yz_kernel<<<dim3(16, 8), 160>>>(w_r1, w_t1, bn_gamma, bn_beta, bn_mean, bn_var);
    gates_kernel<<<dim3(16, 20), 512>>>(w_fh1, w_fw1, w_fh2, w_fw2);
    gemm_kernel<<<dim3(HW / BN, CHN / BM, BB), 256, SMEM_BYTES>>>(rgb, t, w_fuse, out);
}